// round 15
// baseline (speedup 1.0000x reference)
#include <cuda_runtime.h>
#include <cstdint>

#define BB 64
#define PP 256
#define NN 1000
typedef unsigned long long ull;

__device__ float g_K[BB * NN * 128];
__device__ float g_V[BB * NN * 128];
__device__ float g_Q[BB * PP * 128];   // after attnA: holds attention output
#define g_MH g_K                       // mh reuses g_K (dead after attnA)

// ---- f32x2 / memory helpers ----
__device__ __forceinline__ ull ffma2(ull a, ull b, ull c) {
    ull d; asm("fma.rn.f32x2 %0,%1,%2,%3;" : "=l"(d) : "l"(a), "l"(b), "l"(c)); return d;
}
__device__ __forceinline__ ull fmul2(ull a, ull b) {
    ull d; asm("mul.rn.f32x2 %0,%1,%2;" : "=l"(d) : "l"(a), "l"(b)); return d;
}
__device__ __forceinline__ ull pack2(float lo, float hi) {
    ull d; asm("mov.b64 %0,{%1,%2};" : "=l"(d) : "f"(lo), "f"(hi)); return d;
}
__device__ __forceinline__ float hadd2(ull a) {
    float lo, hi; asm("mov.b64 {%0,%1},%2;" : "=f"(lo), "=f"(hi) : "l"(a)); return lo + hi;
}
__device__ __forceinline__ void lds2x64(const float* p, ull& a, ull& b) {
    uint32_t ad = (uint32_t)__cvta_generic_to_shared(p);
    asm("ld.shared.v2.b64 {%0,%1},[%2];" : "=l"(a), "=l"(b) : "r"(ad));
}
__device__ __forceinline__ ull lds64(const float* p) {
    uint32_t ad = (uint32_t)__cvta_generic_to_shared(p);
    ull a; asm("ld.shared.b64 %0,[%1];" : "=l"(a) : "r"(ad)); return a;
}
__device__ __forceinline__ void sts128z(float* p) {
    uint32_t ad = (uint32_t)__cvta_generic_to_shared(p);
    asm volatile("st.shared.v4.b32 [%0],{%1,%1,%1,%1};" :: "r"(ad), "r"(0));
}
__device__ __forceinline__ void sts128v(float* p, float v) {
    uint32_t ad = (uint32_t)__cvta_generic_to_shared(p);
    asm volatile("st.shared.v4.b32 [%0],{%1,%1,%1,%1};" :: "r"(ad), "f"(v));
}
__device__ __forceinline__ void ldg2x64(const float* p, ull& a, ull& b) {
    asm("ld.global.nc.v2.b64 {%0,%1},[%2];" : "=l"(a), "=l"(b) : "l"(p));
}
__device__ __forceinline__ void stg64(float* p, ull v) {
    asm volatile("st.global.b64 [%0],%1;" :: "l"(p), "l"(v));
}
__device__ __forceinline__ void cp16(float* dst, const float* src) {
    uint32_t d = (uint32_t)__cvta_generic_to_shared(dst);
    asm volatile("cp.async.cg.shared.global [%0],[%1],16;" :: "r"(d), "l"(src));
}
__device__ __forceinline__ void cp_commit() { asm volatile("cp.async.commit_group;"); }
template <int N> __device__ __forceinline__ void cp_wait() {
    asm volatile("cp.async.wait_group %0;" :: "n"(N));
}
// tf32 mma: D += A*B (C=D), A row-major, B col-major
__device__ __forceinline__ void mma_tf32(float* d,
        uint32_t a0, uint32_t a1, uint32_t a2, uint32_t a3,
        uint32_t b0, uint32_t b1) {
    asm("mma.sync.aligned.m16n8k8.row.col.f32.tf32.tf32.f32 "
        "{%0,%1,%2,%3},{%4,%5,%6,%7},{%8,%9},{%0,%1,%2,%3};"
        : "+f"(d[0]), "+f"(d[1]), "+f"(d[2]), "+f"(d[3])
        : "r"(a0), "r"(a1), "r"(a2), "r"(a3), "r"(b0), "r"(b1));
}

// ---------------------------------------------------------------------------
// Kernel 1: fused K/V + Q projection (R13 form, ~124us).
// ---------------------------------------------------------------------------
__global__ __launch_bounds__(256) void proj_kernel(
        const float* __restrict__ enc, const float* __restrict__ Wk,
        const float* __restrict__ Wv, const float* __restrict__ last,
        const float* __restrict__ attr, const float* __restrict__ Wq) {
    __shared__ float xs[32 * 128];
    int t = threadIdx.x;

    if (blockIdx.x < 2000) {
        int row0 = blockIdx.x * 32;
        const float4* src = (const float4*)(enc + (size_t)row0 * 128);
        float4* xs4 = (float4*)xs;
#pragma unroll
        for (int i = t; i < 1024; i += 256) xs4[i] = src[i];
        __syncthreads();

        int mat = t >> 7, rh = (t >> 6) & 1, cp = t & 63;
        const float* W = mat ? Wv : Wk;
        float* out = mat ? g_V : g_K;
        const float* xb = xs + rh * 2048;

        ull acc[32];
#pragma unroll
        for (int i = 0; i < 32; i++) acc[i] = 0ull;

#pragma unroll 2
        for (int k = 0; k < 128; k += 2) {
            ull w0 = pack2(W[k * 128 + cp], W[(k + 1) * 128 + cp]);
            ull w1 = pack2(W[k * 128 + cp + 64], W[(k + 1) * 128 + cp + 64]);
#pragma unroll
            for (int r = 0; r < 16; r++) {
                ull x = lds64(xb + r * 128 + k);
                acc[r]      = ffma2(x, w0, acc[r]);
                acc[16 + r] = ffma2(x, w1, acc[16 + r]);
            }
        }
#pragma unroll
        for (int r = 0; r < 16; r++) {
            size_t row = (size_t)(row0 + rh * 16 + r) * 128;
            out[row + cp]      = hadd2(acc[r]);
            out[row + cp + 64] = hadd2(acc[16 + r]);
        }
    } else {
        int row0 = (blockIdx.x - 2000) * 16;
#pragma unroll
        for (int i = t; i < 2048; i += 256) {
            int r = i >> 7, c = i & 127;
            xs[r * 132 + c] = last[(size_t)(row0 + r) * 128 + c];
        }
        if (t < 16) xs[t * 132 + 128] = attr[row0 + t];
        __syncthreads();

        int rh = t >> 7, col = t & 127;
        const float* xr = xs + rh * 8 * 132;
        float acc[8] = {0, 0, 0, 0, 0, 0, 0, 0};
#pragma unroll 4
        for (int in = 0; in < 129; in++) {
            float w = Wq[in * 128 + col];
#pragma unroll
            for (int r = 0; r < 8; r++) acc[r] += xr[r * 132 + in] * w;
        }
#pragma unroll
        for (int r = 0; r < 8; r++)
            g_Q[(size_t)(row0 + rh * 8 + r) * 128 + col] = acc[r];
    }
}

// ---------------------------------------------------------------------------
// Kernel 2: flash attention, 2 queries per lane (R13 form, ~275us).
// ---------------------------------------------------------------------------
__global__ __launch_bounds__(256) void attnA_kernel(
        const float* __restrict__ mask) {
    extern __shared__ float work[];
    int t = threadIdx.x;
    int b = blockIdx.x >> 2;
    int p0 = (blockIdx.x & 3) * 64;
    int h = t >> 5, lane = t & 31;

    const float* Kb = g_K + (size_t)b * NN * 128;
    const float* Vb = g_V + (size_t)b * NN * 128;
    const float* Mb = mask + (size_t)(b * PP + p0) * NN;

    auto stageA = [&](int chunk) {
        int buf = chunk & 1;
        int base = chunk * 32;
        int nv = NN - base; if (nv > 32) nv = 32;
        float* kd = work + buf * 4096;
        float* vd = work + 8192 + buf * 4096;
        float* md = work + 16384 + buf * 2304;
#pragma unroll
        for (int j = 0; j < 4; j++) {
            int i = t + j * 256;
            int n = i >> 5, seg = i & 31;
            if (n < nv) {
                cp16(kd + n * 128 + seg * 4, Kb + (size_t)(base + n) * 128 + seg * 4);
                cp16(vd + n * 128 + seg * 4, Vb + (size_t)(base + n) * 128 + seg * 4);
            } else {
                sts128z(kd + n * 128 + seg * 4);
                sts128z(vd + n * 128 + seg * 4);
            }
        }
#pragma unroll
        for (int j = 0; j < 2; j++) {
            int i = t + j * 256;
            int p = i >> 3, seg = i & 7;
            if (seg * 4 < nv)
                cp16(md + p * 36 + seg * 4, Mb + (size_t)p * NN + base + seg * 4);
            else
                sts128v(md + p * 36 + seg * 4, -1e30f);
        }
    };

    ull qA[8], qB[8];
    {
        const float* qp = g_Q + (size_t)(b * PP + p0 + lane) * 128 + h * 16;
        const float* qp2 = qp + 32 * 128;
        ull c = pack2(0.25f, 0.25f);
#pragma unroll
        for (int j = 0; j < 4; j++) {
            ull a0, a1;
            ldg2x64(qp + 4 * j, a0, a1);
            qA[2 * j]     = fmul2(a0, c);
            qA[2 * j + 1] = fmul2(a1, c);
            ull b0, b1;
            ldg2x64(qp2 + 4 * j, b0, b1);
            qB[2 * j]     = fmul2(b0, c);
            qB[2 * j + 1] = fmul2(b1, c);
        }
    }

    float lA = 0.f, lB = 0.f;
    ull accA[8], accB[8];
#pragma unroll
    for (int j = 0; j < 8; j++) { accA[j] = 0ull; accB[j] = 0ull; }

    stageA(0); cp_commit();
    stageA(1); cp_commit();

    for (int c = 0; c < 32; c++) {
        if (c == 31) cp_wait<0>(); else cp_wait<1>();
        __syncthreads();

        int buf = c & 1;
        const float* k_s = work + buf * 4096;
        const float* v_s = work + 8192 + buf * 4096;
        const float* md  = work + 16384 + buf * 2304;
        const float* mA = md + lane * 36;
        const float* mB = md + (lane + 32) * 36;

#pragma unroll 2
        for (int n = 0; n < 32; n++) {
            const float* kp = k_s + n * 128 + h * 16;
            ull k0, k1, k2, k3, k4, k5, k6, k7;
            lds2x64(kp,      k0, k1);
            lds2x64(kp + 4,  k2, k3);
            lds2x64(kp + 8,  k4, k5);
            lds2x64(kp + 12, k6, k7);
            ull dA = fmul2(qA[0], k0);
            ull dB = fmul2(qB[0], k0);
            dA = ffma2(qA[1], k1, dA); dB = ffma2(qB[1], k1, dB);
            dA = ffma2(qA[2], k2, dA); dB = ffma2(qB[2], k2, dB);
            dA = ffma2(qA[3], k3, dA); dB = ffma2(qB[3], k3, dB);
            dA = ffma2(qA[4], k4, dA); dB = ffma2(qB[4], k4, dB);
            dA = ffma2(qA[5], k5, dA); dB = ffma2(qB[5], k5, dB);
            dA = ffma2(qA[6], k6, dA); dB = ffma2(qB[6], k6, dB);
            dA = ffma2(qA[7], k7, dA); dB = ffma2(qB[7], k7, dB);
            float wA = __expf(hadd2(dA) + mA[n]);
            float wB = __expf(hadd2(dB) + mB[n]);
            lA += wA; lB += wB;
            const float* vp = v_s + n * 128 + h * 16;
            ull v0, v1, v2, v3, v4, v5, v6, v7;
            lds2x64(vp,      v0, v1);
            lds2x64(vp + 4,  v2, v3);
            lds2x64(vp + 8,  v4, v5);
            lds2x64(vp + 12, v6, v7);
            ull wwA = pack2(wA, wA);
            ull wwB = pack2(wB, wB);
            accA[0] = ffma2(wwA, v0, accA[0]); accB[0] = ffma2(wwB, v0, accB[0]);
            accA[1] = ffma2(wwA, v1, accA[1]); accB[1] = ffma2(wwB, v1, accB[1]);
            accA[2] = ffma2(wwA, v2, accA[2]); accB[2] = ffma2(wwB, v2, accB[2]);
            accA[3] = ffma2(wwA, v3, accA[3]); accB[3] = ffma2(wwB, v3, accB[3]);
            accA[4] = ffma2(wwA, v4, accA[4]); accB[4] = ffma2(wwB, v4, accB[4]);
            accA[5] = ffma2(wwA, v5, accA[5]); accB[5] = ffma2(wwB, v5, accB[5]);
            accA[6] = ffma2(wwA, v6, accA[6]); accB[6] = ffma2(wwB, v6, accB[6]);
            accA[7] = ffma2(wwA, v7, accA[7]); accB[7] = ffma2(wwB, v7, accB[7]);
        }
        __syncthreads();
        if (c + 2 < 32) { stageA(c + 2); cp_commit(); }
    }

    {
        float ivA = 1.f / lA, ivB = 1.f / lB;
        ull iA = pack2(ivA, ivA), iB = pack2(ivB, ivB);
        float* opA = g_Q + (size_t)(b * PP + p0 + lane) * 128 + h * 16;
        float* opB = opA + 32 * 128;
#pragma unroll
        for (int j = 0; j < 8; j++) {
            stg64(opA + 2 * j, fmul2(accA[j], iA));
            stg64(opB + 2 * j, fmul2(accB[j], iB));
        }
    }
}

// ---------------------------------------------------------------------------
// Kernel 3: mh = out @ Wo + bo  (unchanged).
// ---------------------------------------------------------------------------
__global__ __launch_bounds__(256) void mh_proj(const float* __restrict__ Wo,
                                               const float* __restrict__ bo) {
    __shared__ float xs[32 * 128];
    int t = threadIdx.x;
    int row0 = blockIdx.x * 32;
    const float4* src = (const float4*)(g_Q + (size_t)row0 * 128);
    float4* xs4 = (float4*)xs;
#pragma unroll
    for (int i = t; i < 1024; i += 256) xs4[i] = src[i];
    __syncthreads();

    int rg = t >> 6, cp = t & 63;
    const float* xb = xs + rg * 8 * 128;

    ull acc[16];
#pragma unroll
    for (int i = 0; i < 16; i++) acc[i] = 0ull;

#pragma unroll 2
    for (int k = 0; k < 128; k += 2) {
        ull w0 = pack2(Wo[k * 128 + cp], Wo[(k + 1) * 128 + cp]);
        ull w1 = pack2(Wo[k * 128 + cp + 64], Wo[(k + 1) * 128 + cp + 64]);
#pragma unroll
        for (int r = 0; r < 8; r++) {
            ull x = lds64(xb + r * 128 + k);
            acc[r]     = ffma2(x, w0, acc[r]);
            acc[8 + r] = ffma2(x, w1, acc[8 + r]);
        }
    }
    float b0 = bo[cp], b1 = bo[cp + 64];
#pragma unroll
    for (int r = 0; r < 8; r++) {
        size_t row = (size_t)(row0 + rg * 8 + r) * 128;
        g_MH[row + cp]      = hadd2(acc[r]) + b0;
        g_MH[row + cp + 64] = hadd2(acc[8 + r]) + b1;
    }
}

// ---------------------------------------------------------------------------
// Kernel 4: scoring via tf32 3-term MMA. block = (b, 64-node slice),
// 1024 blocks, 8 warps. Warp tile = 16p x 32n; 4 mh tiles of 64p.
// S = lo_A*hi_B + hi_A*lo_B + hi_A*hi_B (fp32 accum) -> ~2^-20 rel err.
// smem: enc_hi 8448 | enc_lo 8448 | mh 8448 = 25344 floats (101376 B)
// ---------------------------------------------------------------------------
__global__ __launch_bounds__(256) void phaseB_kernel(
        const float* __restrict__ enc, const float* __restrict__ mask,
        float* __restrict__ probs) {
    extern __shared__ float sm[];
    float* enc_hi = sm;
    float* enc_lo = sm + 8448;
    float* mh_s   = sm + 16896;

    int t = threadIdx.x;
    int b = blockIdx.x >> 4;
    int s = blockIdx.x & 15;
    int base = s * 64;
    int nv = NN - base; if (nv > 64) nv = 64;

    int w = t >> 5, lane = t & 31;
    int g = lane >> 2, tg = lane & 3;
    int pstrip = w >> 1, nstrip = w & 1;

    const float* Eb = enc + (size_t)b * NN * 128;
    const float* Mb = mask + (size_t)b * PP * NN;
    float* pout = probs + (size_t)b * PP * NN;
    const float inv_se = 0.08838834764831845f;
    const uint32_t TMASK = 0xFFFFE000u;

    // stage enc slice raw into enc_hi
#pragma unroll
    for (int j = 0; j < 8; j++) {
        int i = t + j * 256;
        int n = i >> 5, seg = i & 31;
        if (n < nv)
            cp16(enc_hi + n * 132 + seg * 4, Eb + (size_t)(base + n) * 128 + seg * 4);
    }
    cp_commit(); cp_wait<0>();
    __syncthreads();

    // split enc into hi (tf32-truncated) and lo
#pragma unroll
    for (int i = t; i < 8192; i += 256) {
        int row = i >> 7, col = i & 127;
        int idx = row * 132 + col;
        float x = (row < nv) ? enc_hi[idx] : 0.f;
        float hf = __uint_as_float(__float_as_uint(x) & TMASK);
        enc_hi[idx] = hf;
        enc_lo[idx] = x - hf;
    }
    __syncthreads();

    // hoisted B pointers (4 n-subtiles x hi/lo)
    const float* bh[4];
    const float* bl[4];
#pragma unroll
    for (int sub = 0; sub < 4; sub++) {
        int nl = nstrip * 32 + sub * 8 + g;
        bh[sub] = enc_hi + nl * 132;
        bl[sub] = enc_lo + nl * 132;
    }
    const float* arow0 = mh_s + (pstrip * 16 + g) * 132;
    const float* arow1 = arow0 + 8 * 132;

    for (int pt = 0; pt < 4; pt++) {
        __syncthreads();    // previous tile's mh_s reads done
#pragma unroll
        for (int j = 0; j < 8; j++) {
            int i = t + j * 256;
            int row = i >> 5, seg = i & 31;
            cp16(mh_s + row * 132 + seg * 4,
                 g_MH + (size_t)(b * PP + pt * 64 + row) * 128 + seg * 4);
        }
        cp_commit(); cp_wait<0>();
        __syncthreads();

        float c[4][4];
#pragma unroll
        for (int sub = 0; sub < 4; sub++)
#pragma unroll
            for (int j = 0; j < 4; j++) c[sub][j] = 0.f;

#pragma unroll
        for (int ks = 0; ks < 16; ks++) {
            int k0 = ks * 8;
            float xa0 = arow0[k0 + tg];
            float xa1 = arow1[k0 + tg];
            float xa2 = arow0[k0 + tg + 4];
            float xa3 = arow1[k0 + tg + 4];
            uint32_t ah0 = __float_as_uint(xa0) & TMASK;
            uint32_t ah1 = __float_as_uint(xa1) & TMASK;
            uint32_t ah2 = __float_as_uint(xa2) & TMASK;
            uint32_t ah3 = __float_as_uint(xa3) & TMASK;
            uint32_t al0 = __float_as_uint(xa0 - __uint_as_float(ah0));
            uint32_t al1 = __float_as_uint(xa1 - __uint_as_float(ah1));
            uint32_t al2 = __float_as_uint(xa2 - __uint_as_float(ah2));
            uint32_t al3 = __float_as_uint(xa3 - __uint_as_float(ah3));
#pragma unroll
            for (int sub = 0; sub < 4; sub++) {
                uint32_t bh0 = __float_as_uint(bh[sub][k0 + tg]);
                uint32_t bh1 = __float_as_uint(bh[sub][k0 + tg + 4]);
                uint32_t bl0 = __float_as_uint(bl[sub][k0 + tg]);
                uint32_t bl1 = __float_as_uint(bl[sub][k0 + tg + 4]);
                mma_tf32(c[sub], al0, al1, al2, al3, bh0, bh1);
                mma_tf32(c[sub], ah0, ah1, ah2, ah3, bl0, bl1);
                mma_tf32(c[sub], ah0, ah1, ah2, ah3, bh0, bh1);
            }
        }

        // epilogue
        int p_lo = pt * 64 + pstrip * 16 + g;
        int p_hi = p_lo + 8;
#pragma unroll
        for (int sub = 0; sub < 4; sub++) {
            int nl = nstrip * 32 + sub * 8;
            if (nl < nv) {
                int n = base + nl + 2 * tg;
#pragma unroll
                for (int j = 0; j < 4; j++) {
                    int p = (j < 2) ? p_lo : p_hi;
                    int nn = n + (j & 1);
                    float sd = c[sub][j];
                    float x = sd * inv_se;
                    x = fminf(fmaxf(x, -30.f), 30.f);
                    float ex = __expf(-2.f * x);
                    float th = __fdividef(1.f - ex, 1.f + ex);
                    float lg = 10.f * th + Mb[(size_t)p * NN + nn];
                    pout[(size_t)p * NN + nn] = __expf(lg - 10.f);
                }
            }
        }
    }
}

// ---------------------------------------------------------------------------
// Kernel 5: row-sum + rescale (unchanged).
// ---------------------------------------------------------------------------
__global__ __launch_bounds__(256) void norm_kernel(float* __restrict__ probs) {
    int t = threadIdx.x;
    int row0 = blockIdx.x * 32 + (t >> 5) * 4;
    int lane = t & 31;
#pragma unroll
    for (int r = 0; r < 4; r++) {
        float* pr = probs + (size_t)(row0 + r) * NN;
        float sum = 0.f;
        for (int i = lane; i < NN; i += 32) sum += pr[i];
#pragma unroll
        for (int off = 16; off; off >>= 1)
            sum += __shfl_xor_sync(0xFFFFFFFFu, sum, off);
        float inv = 1.f / sum;
        for (int i = lane; i < NN; i += 32) pr[i] *= inv;
    }
}

// ---------------------------------------------------------------------------
extern "C" void kernel_launch(void* const* d_in, const int* in_sizes, int n_in,
                              void* d_out, int out_size) {
    const float* enc  = (const float*)d_in[0];
    const float* last = (const float*)d_in[1];
    const float* attr = (const float*)d_in[2];
    const float* mask = (const float*)d_in[3];
    const float* Wq   = (const float*)d_in[4];
    const float* Wk   = (const float*)d_in[5];
    const float* Wv   = (const float*)d_in[6];
    const float* Wo   = (const float*)d_in[7];
    const float* bo   = (const float*)d_in[8];
    float* out = (float*)d_out;

    cudaFuncSetAttribute(attnA_kernel,
                         cudaFuncAttributeMaxDynamicSharedMemorySize, 83968);
    cudaFuncSetAttribute(phaseB_kernel,
                         cudaFuncAttributeMaxDynamicSharedMemorySize, 101376);

    proj_kernel<<<3024, 256>>>(enc, Wk, Wv, last, attr, Wq);
    attnA_kernel<<<256, 256, 83968>>>(mask);
    mh_proj<<<512, 256>>>(Wo, bo);
    phaseB_kernel<<<1024, 256, 101376>>>(enc, mask, out);
    norm_kernel<<<512, 256>>>(out);
}

// round 16
// speedup vs baseline: 1.5546x; 1.5546x over previous
#include <cuda_runtime.h>
#include <cstdint>

#define BB 64
#define PP 256
#define NN 1000
typedef unsigned long long ull;

__device__ float g_K[BB * NN * 128];
__device__ float g_V[BB * NN * 128];
__device__ float g_Q[BB * PP * 128];   // after attnA: holds attention output
#define g_MH g_K                       // mh reuses g_K (dead after attnA)

// ---- f32x2 / memory helpers ----
__device__ __forceinline__ ull ffma2(ull a, ull b, ull c) {
    ull d; asm("fma.rn.f32x2 %0,%1,%2,%3;" : "=l"(d) : "l"(a), "l"(b), "l"(c)); return d;
}
__device__ __forceinline__ ull fmul2(ull a, ull b) {
    ull d; asm("mul.rn.f32x2 %0,%1,%2;" : "=l"(d) : "l"(a), "l"(b)); return d;
}
__device__ __forceinline__ ull pack2(float lo, float hi) {
    ull d; asm("mov.b64 %0,{%1,%2};" : "=l"(d) : "f"(lo), "f"(hi)); return d;
}
__device__ __forceinline__ float hadd2(ull a) {
    float lo, hi; asm("mov.b64 {%0,%1},%2;" : "=f"(lo), "=f"(hi) : "l"(a)); return lo + hi;
}
__device__ __forceinline__ void lds2x64(const float* p, ull& a, ull& b) {
    uint32_t ad = (uint32_t)__cvta_generic_to_shared(p);
    asm("ld.shared.v2.b64 {%0,%1},[%2];" : "=l"(a), "=l"(b) : "r"(ad));
}
__device__ __forceinline__ ull lds64(const float* p) {
    uint32_t ad = (uint32_t)__cvta_generic_to_shared(p);
    ull a; asm("ld.shared.b64 %0,[%1];" : "=l"(a) : "r"(ad)); return a;
}
__device__ __forceinline__ void sts128z(float* p) {
    uint32_t ad = (uint32_t)__cvta_generic_to_shared(p);
    asm volatile("st.shared.v4.b32 [%0],{%1,%1,%1,%1};" :: "r"(ad), "r"(0));
}
__device__ __forceinline__ void sts128v(float* p, float v) {
    uint32_t ad = (uint32_t)__cvta_generic_to_shared(p);
    asm volatile("st.shared.v4.b32 [%0],{%1,%1,%1,%1};" :: "r"(ad), "f"(v));
}
__device__ __forceinline__ void ldg2x64(const float* p, ull& a, ull& b) {
    asm("ld.global.nc.v2.b64 {%0,%1},[%2];" : "=l"(a), "=l"(b) : "l"(p));
}
__device__ __forceinline__ void stg64(float* p, ull v) {
    asm volatile("st.global.b64 [%0],%1;" :: "l"(p), "l"(v));
}
__device__ __forceinline__ void cp16(float* dst, const float* src) {
    uint32_t d = (uint32_t)__cvta_generic_to_shared(dst);
    asm volatile("cp.async.cg.shared.global [%0],[%1],16;" :: "r"(d), "l"(src));
}
__device__ __forceinline__ void cp_commit() { asm volatile("cp.async.commit_group;"); }
template <int N> __device__ __forceinline__ void cp_wait() {
    asm volatile("cp.async.wait_group %0;" :: "n"(N));
}

// ---------------------------------------------------------------------------
// Kernel 1: fused K/V + Q projection (R13 form).
// ---------------------------------------------------------------------------
__global__ __launch_bounds__(256) void proj_kernel(
        const float* __restrict__ enc, const float* __restrict__ Wk,
        const float* __restrict__ Wv, const float* __restrict__ last,
        const float* __restrict__ attr, const float* __restrict__ Wq) {
    __shared__ float xs[32 * 128];
    int t = threadIdx.x;

    if (blockIdx.x < 2000) {
        int row0 = blockIdx.x * 32;
        const float4* src = (const float4*)(enc + (size_t)row0 * 128);
        float4* xs4 = (float4*)xs;
#pragma unroll
        for (int i = t; i < 1024; i += 256) xs4[i] = src[i];
        __syncthreads();

        int mat = t >> 7, rh = (t >> 6) & 1, cp = t & 63;
        const float* W = mat ? Wv : Wk;
        float* out = mat ? g_V : g_K;
        const float* xb = xs + rh * 2048;

        ull acc[32];
#pragma unroll
        for (int i = 0; i < 32; i++) acc[i] = 0ull;

#pragma unroll 2
        for (int k = 0; k < 128; k += 2) {
            ull w0 = pack2(W[k * 128 + cp], W[(k + 1) * 128 + cp]);
            ull w1 = pack2(W[k * 128 + cp + 64], W[(k + 1) * 128 + cp + 64]);
#pragma unroll
            for (int r = 0; r < 16; r++) {
                ull x = lds64(xb + r * 128 + k);
                acc[r]      = ffma2(x, w0, acc[r]);
                acc[16 + r] = ffma2(x, w1, acc[16 + r]);
            }
        }
#pragma unroll
        for (int r = 0; r < 16; r++) {
            size_t row = (size_t)(row0 + rh * 16 + r) * 128;
            out[row + cp]      = hadd2(acc[r]);
            out[row + cp + 64] = hadd2(acc[16 + r]);
        }
    } else {
        int row0 = (blockIdx.x - 2000) * 16;
#pragma unroll
        for (int i = t; i < 2048; i += 256) {
            int r = i >> 7, c = i & 127;
            xs[r * 132 + c] = last[(size_t)(row0 + r) * 128 + c];
        }
        if (t < 16) xs[t * 132 + 128] = attr[row0 + t];
        __syncthreads();

        int rh = t >> 7, col = t & 127;
        const float* xr = xs + rh * 8 * 132;
        float acc[8] = {0, 0, 0, 0, 0, 0, 0, 0};
#pragma unroll 4
        for (int in = 0; in < 129; in++) {
            float w = Wq[in * 128 + col];
#pragma unroll
            for (int r = 0; r < 8; r++) acc[r] += xr[r * 132 + in] * w;
        }
#pragma unroll
        for (int r = 0; r < 8; r++)
            g_Q[(size_t)(row0 + rh * 8 + r) * 128 + col] = acc[r];
    }
}

// ---------------------------------------------------------------------------
// Kernel 2: flash attention, 2 queries per lane, inner loop batched by 2 n.
// 64-q tiles, 256 blocks. warp = head h; lane owns queries (lane, lane+32).
// smem floats: k0/k1 4096 ea | v0/v1 4096 ea | m0/m1 2304 ea = 20992 (83968 B)
// ---------------------------------------------------------------------------
__global__ __launch_bounds__(256) void attnA_kernel(
        const float* __restrict__ mask) {
    extern __shared__ float work[];
    int t = threadIdx.x;
    int b = blockIdx.x >> 2;
    int p0 = (blockIdx.x & 3) * 64;
    int h = t >> 5, lane = t & 31;

    const float* Kb = g_K + (size_t)b * NN * 128;
    const float* Vb = g_V + (size_t)b * NN * 128;
    const float* Mb = mask + (size_t)(b * PP + p0) * NN;

    auto stageA = [&](int chunk) {
        int buf = chunk & 1;
        int base = chunk * 32;
        int nv = NN - base; if (nv > 32) nv = 32;
        float* kd = work + buf * 4096;
        float* vd = work + 8192 + buf * 4096;
        float* md = work + 16384 + buf * 2304;
#pragma unroll
        for (int j = 0; j < 4; j++) {
            int i = t + j * 256;
            int n = i >> 5, seg = i & 31;
            if (n < nv) {
                cp16(kd + n * 128 + seg * 4, Kb + (size_t)(base + n) * 128 + seg * 4);
                cp16(vd + n * 128 + seg * 4, Vb + (size_t)(base + n) * 128 + seg * 4);
            } else {
                sts128z(kd + n * 128 + seg * 4);
                sts128z(vd + n * 128 + seg * 4);
            }
        }
#pragma unroll
        for (int j = 0; j < 2; j++) {
            int i = t + j * 256;
            int p = i >> 3, seg = i & 7;
            if (seg * 4 < nv)
                cp16(md + p * 36 + seg * 4, Mb + (size_t)p * NN + base + seg * 4);
            else
                sts128v(md + p * 36 + seg * 4, -1e30f);
        }
    };

    ull qA[8], qB[8];
    {
        const float* qp = g_Q + (size_t)(b * PP + p0 + lane) * 128 + h * 16;
        const float* qp2 = qp + 32 * 128;
        ull c = pack2(0.25f, 0.25f);
#pragma unroll
        for (int j = 0; j < 4; j++) {
            ull a0, a1;
            ldg2x64(qp + 4 * j, a0, a1);
            qA[2 * j]     = fmul2(a0, c);
            qA[2 * j + 1] = fmul2(a1, c);
            ull b0, b1;
            ldg2x64(qp2 + 4 * j, b0, b1);
            qB[2 * j]     = fmul2(b0, c);
            qB[2 * j + 1] = fmul2(b1, c);
        }
    }

    float lA = 0.f, lB = 0.f;
    ull accA[8], accB[8];
#pragma unroll
    for (int j = 0; j < 8; j++) { accA[j] = 0ull; accB[j] = 0ull; }

    stageA(0); cp_commit();
    stageA(1); cp_commit();

    for (int c = 0; c < 32; c++) {
        if (c == 31) cp_wait<0>(); else cp_wait<1>();
        __syncthreads();

        int buf = c & 1;
        const float* k_s = work + buf * 4096;
        const float* v_s = work + 8192 + buf * 4096;
        const float* md  = work + 16384 + buf * 2304;
        const float* mA = md + lane * 36;
        const float* mB = md + (lane + 32) * 36;

#pragma unroll 2
        for (int ng = 0; ng < 16; ng++) {
            int n0 = 2 * ng, n1 = 2 * ng + 1;
            // score chains for n0 (2 q)
            float sA0, sB0, sA1, sB1;
            {
                const float* kp = k_s + n0 * 128 + h * 16;
                ull k0, k1, k2, k3, k4, k5, k6, k7;
                lds2x64(kp,      k0, k1);
                lds2x64(kp + 4,  k2, k3);
                lds2x64(kp + 8,  k4, k5);
                lds2x64(kp + 12, k6, k7);
                ull dA = fmul2(qA[0], k0);
                ull dB = fmul2(qB[0], k0);
                dA = ffma2(qA[1], k1, dA); dB = ffma2(qB[1], k1, dB);
                dA = ffma2(qA[2], k2, dA); dB = ffma2(qB[2], k2, dB);
                dA = ffma2(qA[3], k3, dA); dB = ffma2(qB[3], k3, dB);
                dA = ffma2(qA[4], k4, dA); dB = ffma2(qB[4], k4, dB);
                dA = ffma2(qA[5], k5, dA); dB = ffma2(qB[5], k5, dB);
                dA = ffma2(qA[6], k6, dA); dB = ffma2(qB[6], k6, dB);
                dA = ffma2(qA[7], k7, dA); dB = ffma2(qB[7], k7, dB);
                sA0 = hadd2(dA) + mA[n0];
                sB0 = hadd2(dB) + mB[n0];
            }
            // score chains for n1 (2 q)
            {
                const float* kp = k_s + n1 * 128 + h * 16;
                ull k0, k1, k2, k3, k4, k5, k6, k7;
                lds2x64(kp,      k0, k1);
                lds2x64(kp + 4,  k2, k3);
                lds2x64(kp + 8,  k4, k5);
                lds2x64(kp + 12, k6, k7);
                ull dA = fmul2(qA[0], k0);
                ull dB = fmul2(qB[0], k0);
                dA = ffma2(qA[1], k1, dA); dB = ffma2(qB[1], k1, dB);
                dA = ffma2(qA[2], k2, dA); dB = ffma2(qB[2], k2, dB);
                dA = ffma2(qA[3], k3, dA); dB = ffma2(qB[3], k3, dB);
                dA = ffma2(qA[4], k4, dA); dB = ffma2(qB[4], k4, dB);
                dA = ffma2(qA[5], k5, dA); dB = ffma2(qB[5], k5, dB);
                dA = ffma2(qA[6], k6, dA); dB = ffma2(qB[6], k6, dB);
                dA = ffma2(qA[7], k7, dA); dB = ffma2(qB[7], k7, dB);
                sA1 = hadd2(dA) + mA[n1];
                sB1 = hadd2(dB) + mB[n1];
            }
            // 4 independent exps
            float wA0 = __expf(sA0);
            float wB0 = __expf(sB0);
            float wA1 = __expf(sA1);
            float wB1 = __expf(sB1);
            lA += wA0 + wA1;
            lB += wB0 + wB1;
            // V accumulation n0
            {
                const float* vp = v_s + n0 * 128 + h * 16;
                ull v0, v1, v2, v3, v4, v5, v6, v7;
                lds2x64(vp,      v0, v1);
                lds2x64(vp + 4,  v2, v3);
                lds2x64(vp + 8,  v4, v5);
                lds2x64(vp + 12, v6, v7);
                ull wwA = pack2(wA0, wA0);
                ull wwB = pack2(wB0, wB0);
                accA[0] = ffma2(wwA, v0, accA[0]); accB[0] = ffma2(wwB, v0, accB[0]);
                accA[1] = ffma2(wwA, v1, accA[1]); accB[1] = ffma2(wwB, v1, accB[1]);
                accA[2] = ffma2(wwA, v2, accA[2]); accB[2] = ffma2(wwB, v2, accB[2]);
                accA[3] = ffma2(wwA, v3, accA[3]); accB[3] = ffma2(wwB, v3, accB[3]);
                accA[4] = ffma2(wwA, v4, accA[4]); accB[4] = ffma2(wwB, v4, accB[4]);
                accA[5] = ffma2(wwA, v5, accA[5]); accB[5] = ffma2(wwB, v5, accB[5]);
                accA[6] = ffma2(wwA, v6, accA[6]); accB[6] = ffma2(wwB, v6, accB[6]);
                accA[7] = ffma2(wwA, v7, accA[7]); accB[7] = ffma2(wwB, v7, accB[7]);
            }
            // V accumulation n1
            {
                const float* vp = v_s + n1 * 128 + h * 16;
                ull v0, v1, v2, v3, v4, v5, v6, v7;
                lds2x64(vp,      v0, v1);
                lds2x64(vp + 4,  v2, v3);
                lds2x64(vp + 8,  v4, v5);
                lds2x64(vp + 12, v6, v7);
                ull wwA = pack2(wA1, wA1);
                ull wwB = pack2(wB1, wB1);
                accA[0] = ffma2(wwA, v0, accA[0]); accB[0] = ffma2(wwB, v0, accB[0]);
                accA[1] = ffma2(wwA, v1, accA[1]); accB[1] = ffma2(wwB, v1, accB[1]);
                accA[2] = ffma2(wwA, v2, accA[2]); accB[2] = ffma2(wwB, v2, accB[2]);
                accA[3] = ffma2(wwA, v3, accA[3]); accB[3] = ffma2(wwB, v3, accB[3]);
                accA[4] = ffma2(wwA, v4, accA[4]); accB[4] = ffma2(wwB, v4, accB[4]);
                accA[5] = ffma2(wwA, v5, accA[5]); accB[5] = ffma2(wwB, v5, accB[5]);
                accA[6] = ffma2(wwA, v6, accA[6]); accB[6] = ffma2(wwB, v6, accB[6]);
                accA[7] = ffma2(wwA, v7, accA[7]); accB[7] = ffma2(wwB, v7, accB[7]);
            }
        }
        __syncthreads();
        if (c + 2 < 32) { stageA(c + 2); cp_commit(); }
    }

    {
        float ivA = 1.f / lA, ivB = 1.f / lB;
        ull iA = pack2(ivA, ivA), iB = pack2(ivB, ivB);
        float* opA = g_Q + (size_t)(b * PP + p0 + lane) * 128 + h * 16;
        float* opB = opA + 32 * 128;
#pragma unroll
        for (int j = 0; j < 8; j++) {
            stg64(opA + 2 * j, fmul2(accA[j], iA));
            stg64(opB + 2 * j, fmul2(accB[j], iB));
        }
    }
}

// ---------------------------------------------------------------------------
// Kernel 3: mh = out @ Wo + bo  (R13 form).
// ---------------------------------------------------------------------------
__global__ __launch_bounds__(256) void mh_proj(const float* __restrict__ Wo,
                                               const float* __restrict__ bo) {
    __shared__ float xs[32 * 128];
    int t = threadIdx.x;
    int row0 = blockIdx.x * 32;
    const float4* src = (const float4*)(g_Q + (size_t)row0 * 128);
    float4* xs4 = (float4*)xs;
#pragma unroll
    for (int i = t; i < 1024; i += 256) xs4[i] = src[i];
    __syncthreads();

    int rg = t >> 6, cp = t & 63;
    const float* xb = xs + rg * 8 * 128;

    ull acc[16];
#pragma unroll
    for (int i = 0; i < 16; i++) acc[i] = 0ull;

#pragma unroll 2
    for (int k = 0; k < 128; k += 2) {
        ull w0 = pack2(Wo[k * 128 + cp], Wo[(k + 1) * 128 + cp]);
        ull w1 = pack2(Wo[k * 128 + cp + 64], Wo[(k + 1) * 128 + cp + 64]);
#pragma unroll
        for (int r = 0; r < 8; r++) {
            ull x = lds64(xb + r * 128 + k);
            acc[r]     = ffma2(x, w0, acc[r]);
            acc[8 + r] = ffma2(x, w1, acc[8 + r]);
        }
    }
    float b0 = bo[cp], b1 = bo[cp + 64];
#pragma unroll
    for (int r = 0; r < 8; r++) {
        size_t row = (size_t)(row0 + rg * 8 + r) * 128;
        g_MH[row + cp]      = hadd2(acc[r]) + b0;
        g_MH[row + cp + 64] = hadd2(acc[8 + r]) + b1;
    }
}

// ---------------------------------------------------------------------------
// Kernel 4: scoring (R13 form): loop-inverted, 64-row mh tiles.
// block = (b, 64-node slice), 1024 blocks; thread = 8p x 2n; 4 tiles.
// smem: enc 8448 | mh 8448 = 16896 floats (67584 B), 3 CTAs/SM.
// ---------------------------------------------------------------------------
__global__ __launch_bounds__(256, 3) void phaseB_kernel(
        const float* __restrict__ enc, const float* __restrict__ mask,
        float* __restrict__ probs) {
    extern __shared__ float sm[];
    float* enc_s = sm;
    float* mh_s  = sm + 8448;

    int t = threadIdx.x;
    int b = blockIdx.x >> 4;
    int s = blockIdx.x & 15;
    int base = s * 64;
    int nv = NN - base; if (nv > 64) nv = 64;
    int pq = t >> 5, nh = t & 31;

    const float* Eb = enc + (size_t)b * NN * 128;
    const float* Mb = mask + (size_t)b * PP * NN;
    float* pout = probs + (size_t)b * PP * NN;
    const float inv_se = 0.08838834764831845f;

    // stage enc slice (once)
#pragma unroll
    for (int j = 0; j < 8; j++) {
        int i = t + j * 256;
        int n = i >> 5, seg = i & 31;
        if (n < nv)
            cp16(enc_s + n * 132 + seg * 4, Eb + (size_t)(base + n) * 128 + seg * 4);
    }
    cp_commit();

    const float* e0p = enc_s + nh * 132;
    const float* e1p = enc_s + (nh + 32) * 132;

    for (int pt = 0; pt < 4; pt++) {
        __syncthreads();    // previous tile's mh_s reads done
#pragma unroll
        for (int j = 0; j < 8; j++) {
            int i = t + j * 256;
            int row = i >> 5, seg = i & 31;
            cp16(mh_s + row * 132 + seg * 4,
                 g_MH + (size_t)(b * PP + pt * 64 + row) * 128 + seg * 4);
        }
        cp_commit(); cp_wait<0>();
        __syncthreads();

        const float* mrow = mh_s + (8 * pq) * 132;
        ull a[8][2];
#pragma unroll
        for (int pp = 0; pp < 8; pp++) { a[pp][0] = 0ull; a[pp][1] = 0ull; }

#pragma unroll 2
        for (int k = 0; k < 128; k += 4) {
            ull e00, e01, e10, e11;
            lds2x64(e0p + k, e00, e01);
            lds2x64(e1p + k, e10, e11);
#pragma unroll
            for (int pp = 0; pp < 8; pp++) {
                ull m0, m1;
                lds2x64(mrow + pp * 132 + k, m0, m1);
                a[pp][0] = ffma2(m0, e00, a[pp][0]);
                a[pp][0] = ffma2(m1, e01, a[pp][0]);
                a[pp][1] = ffma2(m0, e10, a[pp][1]);
                a[pp][1] = ffma2(m1, e11, a[pp][1]);
            }
        }
#pragma unroll
        for (int j = 0; j < 2; j++) {
            int n = nh + 32 * j;
            if (n < nv) {
#pragma unroll
                for (int pp = 0; pp < 8; pp++) {
                    int p = pt * 64 + 8 * pq + pp;
                    float sd = hadd2(a[pp][j]);
                    float x = sd * inv_se;
                    x = fminf(fmaxf(x, -30.f), 30.f);
                    float ex = __expf(-2.f * x);
                    float th = __fdividef(1.f - ex, 1.f + ex);
                    float lg = 10.f * th + Mb[(size_t)p * NN + base + n];
                    pout[(size_t)p * NN + base + n] = __expf(lg - 10.f);
                }
            }
        }
    }
}

// ---------------------------------------------------------------------------
// Kernel 5: row-sum + rescale (unchanged).
// ---------------------------------------------------------------------------
__global__ __launch_bounds__(256) void norm_kernel(float* __restrict__ probs) {
    int t = threadIdx.x;
    int row0 = blockIdx.x * 32 + (t >> 5) * 4;
    int lane = t & 31;
#pragma unroll
    for (int r = 0; r < 4; r++) {
        float* pr = probs + (size_t)(row0 + r) * NN;
        float sum = 0.f;
        for (int i = lane; i < NN; i += 32) sum += pr[i];
#pragma unroll
        for (int off = 16; off; off >>= 1)
            sum += __shfl_xor_sync(0xFFFFFFFFu, sum, off);
        float inv = 1.f / sum;
        for (int i = lane; i < NN; i += 32) pr[i] *= inv;
    }
}

// ---------------------------------------------------------------------------
extern "C" void kernel_launch(void* const* d_in, const int* in_sizes, int n_in,
                              void* d_out, int out_size) {
    const float* enc  = (const float*)d_in[0];
    const float* last = (const float*)d_in[1];
    const float* attr = (const float*)d_in[2];
    const float* mask = (const float*)d_in[3];
    const float* Wq   = (const float*)d_in[4];
    const float* Wk   = (const float*)d_in[5];
    const float* Wv   = (const float*)d_in[6];
    const float* Wo   = (const float*)d_in[7];
    const float* bo   = (const float*)d_in[8];
    float* out = (float*)d_out;

    cudaFuncSetAttribute(attnA_kernel,
                         cudaFuncAttributeMaxDynamicSharedMemorySize, 83968);
    cudaFuncSetAttribute(phaseB_kernel,
                         cudaFuncAttributeMaxDynamicSharedMemorySize, 67584);

    proj_kernel<<<3024, 256>>>(enc, Wk, Wv, last, attr, Wq);
    attnA_kernel<<<256, 256, 83968>>>(mask);
    mh_proj<<<512, 256>>>(Wo, bo);
    phaseB_kernel<<<1024, 256, 67584>>>(enc, mask, out);
    norm_kernel<<<512, 256>>>(out);
}